// round 1
// baseline (speedup 1.0000x reference)
#include <cuda_runtime.h>
#include <cstdint>
#include <math.h>

// Problem constants
#define BATCH 4
#define SEQ   2048
#define HID   2048
#define INTER 5504
#define MTOK  (BATCH*SEQ)          // 8192
#define OUT_ELEMS ((long)MTOK*HID) // 16777216

// GEMM tiling
#define BM 128
#define BN 128
#define BK 32
#define LDSW 36   // 32 + 4 pad (keeps float4 alignment: 36*4B % 16 == 0)

// Scratch (allocation-free rule: __device__ globals)
__device__ float g_buf1[(long)MTOK * INTER];  // gate -> intermediate (in place)
__device__ float g_buf2[(long)MTOK * INTER];  // up
__device__ float g_rowsq[INTER];

__device__ __forceinline__ uint32_t f2tf32(float x) {
    uint32_t r;
    asm("cvt.rna.tf32.f32 %0, %1;" : "=r"(r) : "f"(x));
    return r;
}

__device__ __forceinline__ void mma_tf32(float c[4],
                                         uint32_t a0, uint32_t a1, uint32_t a2, uint32_t a3,
                                         uint32_t b0, uint32_t b1) {
    asm volatile(
        "mma.sync.aligned.m16n8k8.row.col.f32.tf32.tf32.f32 "
        "{%0,%1,%2,%3}, {%4,%5,%6,%7}, {%8,%9}, {%0,%1,%2,%3};"
        : "+f"(c[0]), "+f"(c[1]), "+f"(c[2]), "+f"(c[3])
        : "r"(a0), "r"(a1), "r"(a2), "r"(a3), "r"(b0), "r"(b1));
}

// C[M,N] = A[M,K] * B[N,K]^T   (A row-major, B row-major with K contiguous)
// Requirements: M%128==0, N%128==0, K%32==0 (all true for this problem).
__global__ __launch_bounds__(256, 1)
void gemm_tn_tf32(const float* __restrict__ A, const float* __restrict__ B,
                  float* __restrict__ C, int M, int N, int K)
{
    __shared__ uint32_t As[BM][LDSW];
    __shared__ uint32_t Bs[BN][LDSW];

    const int tid  = threadIdx.x;
    const int wid  = tid >> 5;
    const int lane = tid & 31;
    const int grp  = lane >> 2;   // 0..7
    const int tig  = lane & 3;    // 0..3
    const int wm   = wid >> 2;    // 0..1  (m-dimension warp)
    const int wn   = wid & 3;     // 0..3  (n-dimension warp)

    const long bm = (long)blockIdx.y * BM;
    const long bn = (long)blockIdx.x * BN;
    const float* Ab = A + bm * K;
    const float* Bb = B + bn * K;

    float acc[4][4][4];
#pragma unroll
    for (int mi = 0; mi < 4; mi++)
#pragma unroll
        for (int ni = 0; ni < 4; ni++)
#pragma unroll
            for (int r = 0; r < 4; r++) acc[mi][ni][r] = 0.f;

    const int ldrow = tid >> 3;        // 0..31
    const int ldcol = (tid & 7) * 4;   // 0,4,...,28

    float4 ar[4], br[4];
#pragma unroll
    for (int p = 0; p < 4; p++) {
        ar[p] = *(const float4*)(Ab + (long)(ldrow + p * 32) * K + ldcol);
        br[p] = *(const float4*)(Bb + (long)(ldrow + p * 32) * K + ldcol);
    }

    const int nK = K / BK;
    for (int t = 0; t < nK; t++) {
        // stage to smem (convert to tf32 bits, vectorized 16B store)
#pragma unroll
        for (int p = 0; p < 4; p++) {
            int r = ldrow + p * 32;
            uint4 av = make_uint4(f2tf32(ar[p].x), f2tf32(ar[p].y), f2tf32(ar[p].z), f2tf32(ar[p].w));
            uint4 bv = make_uint4(f2tf32(br[p].x), f2tf32(br[p].y), f2tf32(br[p].z), f2tf32(br[p].w));
            *(uint4*)&As[r][ldcol] = av;
            *(uint4*)&Bs[r][ldcol] = bv;
        }
        __syncthreads();

        // prefetch next K-slab while computing this one
        if (t + 1 < nK) {
            const float* An = Ab + (t + 1) * BK;
            const float* Bn = Bb + (t + 1) * BK;
#pragma unroll
            for (int p = 0; p < 4; p++) {
                ar[p] = *(const float4*)(An + (long)(ldrow + p * 32) * K + ldcol);
                br[p] = *(const float4*)(Bn + (long)(ldrow + p * 32) * K + ldcol);
            }
        }

#pragma unroll
        for (int ks = 0; ks < 4; ks++) {
            const int k0 = ks * 8;
            uint32_t af[4][4];
            uint32_t bf[4][2];
#pragma unroll
            for (int mi = 0; mi < 4; mi++) {
                int r = wm * 64 + mi * 16 + grp;
                af[mi][0] = As[r][k0 + tig];
                af[mi][1] = As[r + 8][k0 + tig];
                af[mi][2] = As[r][k0 + tig + 4];
                af[mi][3] = As[r + 8][k0 + tig + 4];
            }
#pragma unroll
            for (int ni = 0; ni < 4; ni++) {
                int c = wn * 32 + ni * 8 + grp;
                bf[ni][0] = Bs[c][k0 + tig];
                bf[ni][1] = Bs[c][k0 + tig + 4];
            }
#pragma unroll
            for (int mi = 0; mi < 4; mi++)
#pragma unroll
                for (int ni = 0; ni < 4; ni++)
                    mma_tf32(acc[mi][ni], af[mi][0], af[mi][1], af[mi][2], af[mi][3],
                             bf[ni][0], bf[ni][1]);
        }
        __syncthreads();
    }

    // epilogue
#pragma unroll
    for (int mi = 0; mi < 4; mi++) {
#pragma unroll
        for (int ni = 0; ni < 4; ni++) {
            long row = bm + wm * 64 + mi * 16 + grp;
            long col = bn + wn * 32 + ni * 8 + tig * 2;
            C[row * N + col]           = acc[mi][ni][0];
            C[row * N + col + 1]       = acc[mi][ni][1];
            C[(row + 8) * N + col]     = acc[mi][ni][2];
            C[(row + 8) * N + col + 1] = acc[mi][ni][3];
        }
    }
}

// intermediate = silu(gate) * up, written over gate buffer
__global__ void swiglu_kernel(float* __restrict__ gate_io, const float* __restrict__ up, long n4)
{
    long i = (long)blockIdx.x * blockDim.x + threadIdx.x;
    if (i >= n4) return;
    float4 g = ((const float4*)gate_io)[i];
    float4 u = ((const float4*)up)[i];
    float4 r;
    r.x = (g.x / (1.f + expf(-g.x))) * u.x;
    r.y = (g.y / (1.f + expf(-g.y))) * u.y;
    r.z = (g.z / (1.f + expf(-g.z))) * u.z;
    r.w = (g.w / (1.f + expf(-g.w))) * u.w;
    ((float4*)gate_io)[i] = r;
}

// row_sq[i] = sum_h w_up[i,h]^2   (one warp per row)
__global__ void rowsq_kernel(const float* __restrict__ wup, float* __restrict__ out)
{
    int row  = blockIdx.x * 8 + (threadIdx.x >> 5);
    int lane = threadIdx.x & 31;
    if (row >= INTER) return;
    const float4* p = (const float4*)(wup + (long)row * HID);
    float s = 0.f;
#pragma unroll 4
    for (int j = lane; j < HID / 4; j += 32) {
        float4 v = p[j];
        s += v.x * v.x + v.y * v.y + v.z * v.z + v.w * v.w;
    }
#pragma unroll
    for (int off = 16; off > 0; off >>= 1)
        s += __shfl_xor_sync(0xffffffffu, s, off);
    if (lane == 0) out[row] = s;
}

// impacts[b,i] = sqrt( sum_s inter[b,s,i]^2 * row_sq[i] )
__global__ void impacts_kernel(const float* __restrict__ inter,
                               const float* __restrict__ rowsq,
                               float* __restrict__ out)
{
    int idx = blockIdx.x * blockDim.x + threadIdx.x;
    if (idx >= BATCH * INTER) return;
    int b = idx / INTER;
    int i = idx - b * INTER;
    const float* p = inter + (long)b * SEQ * INTER + i;
    float s = 0.f;
#pragma unroll 8
    for (int t = 0; t < SEQ; t++) {
        float v = p[(long)t * INTER];
        s += v * v;
    }
    out[idx] = sqrtf(s * rowsq[i]);
}

extern "C" void kernel_launch(void* const* d_in, const int* in_sizes, int n_in,
                              void* d_out, int out_size)
{
    const float* X  = (const float*)d_in[0];  // [B,S,H]
    const float* Wg = (const float*)d_in[1];  // [I,H]
    const float* Wu = (const float*)d_in[2];  // [I,H]
    const float* Wd = (const float*)d_in[3];  // [H,I]
    float* out = (float*)d_out;

    float *buf1, *buf2, *rsq;
    cudaGetSymbolAddress((void**)&buf1, g_buf1);
    cudaGetSymbolAddress((void**)&buf2, g_buf2);
    cudaGetSymbolAddress((void**)&rsq, g_rowsq);

    // 1) gate = X * Wg^T ; up = X * Wu^T
    dim3 grid1(INTER / BN, MTOK / BM);   // 43 x 64
    gemm_tn_tf32<<<grid1, 256>>>(X, Wg, buf1, MTOK, INTER, HID);
    gemm_tn_tf32<<<grid1, 256>>>(X, Wu, buf2, MTOK, INTER, HID);

    // 2) inter = silu(gate) * up   (in place over buf1)
    long n4 = (long)MTOK * INTER / 4;
    swiglu_kernel<<<(unsigned)((n4 + 255) / 256), 256>>>(buf1, buf2, n4);

    // 3) impacts
    rowsq_kernel<<<(INTER + 7) / 8, 256>>>(Wu, rsq);
    impacts_kernel<<<(BATCH * INTER + 255) / 256, 256>>>(buf1, rsq, out + OUT_ELEMS);

    // 4) out = inter * Wd^T
    dim3 grid2(HID / BN, MTOK / BM);     // 16 x 64
    gemm_tn_tf32<<<grid2, 256>>>(buf1, Wd, out, MTOK, HID, INTER);
}

// round 3
// speedup vs baseline: 1.3849x; 1.3849x over previous
#include <cuda_runtime.h>
#include <cstdint>
#include <math.h>

#define BATCH 4
#define SEQ   2048
#define HID   2048
#define INTER 5504
#define MTOK  (BATCH*SEQ)            // 8192
#define OUT_ELEMS ((long)MTOK*HID)   // 16777216

#define LDSW 36                      // 32 + 4 pad words
#define TSZ  (128*LDSW)              // words per 128x32 tile stage = 4608

// ---------------- scratch ----------------
__device__ float g_Xc [(long)MTOK*HID];
__device__ float g_Wgc[(long)INTER*HID];
__device__ float g_Wuc[(long)INTER*HID];
__device__ float g_Wdc[(long)HID*INTER];
__device__ float g_inter[(long)MTOK*INTER];
__device__ float g_rowsq[INTER];
__device__ float g_part [32L*INTER];

// ---------------- helpers ----------------
__device__ __forceinline__ uint32_t smem_u32(const void* p){
    uint32_t a;
    asm("{ .reg .u64 t; cvta.to.shared.u64 t, %1; cvt.u32.u64 %0, t; }" : "=r"(a) : "l"(p));
    return a;
}
__device__ __forceinline__ uint32_t f2tf32(float x){
    uint32_t r; asm("cvt.rna.tf32.f32 %0, %1;" : "=r"(r) : "f"(x)); return r;
}
__device__ __forceinline__ void cpa16(uint32_t dst, const void* src){
    asm volatile("cp.async.cg.shared.global [%0], [%1], 16;" :: "r"(dst), "l"(src));
}
__device__ __forceinline__ void mma_tf32(float c[4],
                                         uint32_t a0, uint32_t a1, uint32_t a2, uint32_t a3,
                                         uint32_t b0, uint32_t b1) {
    asm volatile(
        "mma.sync.aligned.m16n8k8.row.col.f32.tf32.tf32.f32 "
        "{%0,%1,%2,%3}, {%4,%5,%6,%7}, {%8,%9}, {%0,%1,%2,%3};"
        : "+f"(c[0]), "+f"(c[1]), "+f"(c[2]), "+f"(c[3])
        : "r"(a0), "r"(a1), "r"(a2), "r"(a3), "r"(b0), "r"(b1));
}
#define CP_COMMIT() asm volatile("cp.async.commit_group;" ::: "memory")
#define CP_WAIT2()  asm volatile("cp.async.wait_group 2;" ::: "memory")

// ============================================================================
// Fused gate/up GEMM + SwiGLU epilogue.
// Block: 128 rows x 128 cols (both Dg and Du). 256 thr, warps 2x4, warp 64x32.
// smem: 3 stages x (A + Bg + Bu) each 128x32 fp32 (padded rows).
// ============================================================================
#define GU_SMEM_BYTES (9*TSZ*4)   // 165888

__global__ void __launch_bounds__(256,1)
gemm_gu(const float* __restrict__ X, const float* __restrict__ Wg,
        const float* __restrict__ Wu, float* __restrict__ inter)
{
    extern __shared__ float smem[];
    const uint32_t sb = smem_u32(smem);

    const int tid  = threadIdx.x;
    const int wid  = tid >> 5;
    const int lane = tid & 31;
    const int grp  = lane >> 2;
    const int tig  = lane & 3;
    const int wm   = wid >> 2;    // 0..1
    const int wn   = wid & 3;     // 0..3

    // group-swizzled tile mapping: groups of 16 bm-rows x all 43 bn
    const int NBN = INTER/128;    // 43
    const int GM  = 16;
    int bid = blockIdx.x;
    int g   = bid / (GM*NBN);
    int r   = bid % (GM*NBN);
    const long bm = (long)(g*GM + (r % GM)) * 128;
    const int  bn = (r / GM) * 128;

    const int ldr = tid >> 3;        // 0..31
    const int ldc = tid & 7;         // 0..7

    const float* Ag = X  + (bm + ldr)*(long)HID + ldc*4;
    const float* Gg = Wg + (long)(bn + ldr)*HID + ldc*4;
    const float* Ug = Wu + (long)(bn + ldr)*HID + ldc*4;
    const uint32_t dstA = sb + (ldr*LDSW + ldc*4)*4;

    float acc_g[4][4][4], acc_u[4][4][4];
#pragma unroll
    for (int mi = 0; mi < 4; mi++)
#pragma unroll
        for (int ni = 0; ni < 4; ni++)
#pragma unroll
            for (int q = 0; q < 4; q++) { acc_g[mi][ni][q] = 0.f; acc_u[mi][ni][q] = 0.f; }

    const int nK = HID/32;   // 64

    // preload stages 0..2
#pragma unroll
    for (int p = 0; p < 3; p++) {
        const int k0 = p*32;
#pragma unroll
        for (int i = 0; i < 4; i++) {
            cpa16(dstA + (p*TSZ + i*32*LDSW)*4,           Ag + (long)i*32*HID + k0);
            cpa16(dstA + ((3+p)*TSZ + i*32*LDSW)*4,       Gg + (long)i*32*HID + k0);
            cpa16(dstA + ((6+p)*TSZ + i*32*LDSW)*4,       Ug + (long)i*32*HID + k0);
        }
        CP_COMMIT();
    }

    for (int j = 0; j < nK; j++) {
        const int s = j % 3;
        CP_WAIT2();
        __syncthreads();

        const float* As = smem + s*TSZ;
        const float* Gs = smem + (3+s)*TSZ;
        const float* Us = smem + (6+s)*TSZ;

#pragma unroll
        for (int ks = 0; ks < 4; ks++) {
            const int k0 = ks*8;
            uint32_t af[4][4], bg[4][2], bu[4][2];
#pragma unroll
            for (int mi = 0; mi < 4; mi++) {
                int rr = wm*64 + mi*16 + grp;
                af[mi][0] = __float_as_uint(As[rr*LDSW + k0 + tig]);
                af[mi][1] = __float_as_uint(As[(rr+8)*LDSW + k0 + tig]);
                af[mi][2] = __float_as_uint(As[rr*LDSW + k0 + tig + 4]);
                af[mi][3] = __float_as_uint(As[(rr+8)*LDSW + k0 + tig + 4]);
            }
#pragma unroll
            for (int ni = 0; ni < 4; ni++) {
                int cc = wn*32 + ni*8 + grp;
                bg[ni][0] = __float_as_uint(Gs[cc*LDSW + k0 + tig]);
                bg[ni][1] = __float_as_uint(Gs[cc*LDSW + k0 + tig + 4]);
                bu[ni][0] = __float_as_uint(Us[cc*LDSW + k0 + tig]);
                bu[ni][1] = __float_as_uint(Us[cc*LDSW + k0 + tig + 4]);
            }
#pragma unroll
            for (int mi = 0; mi < 4; mi++)
#pragma unroll
                for (int ni = 0; ni < 4; ni++) {
                    mma_tf32(acc_g[mi][ni], af[mi][0], af[mi][1], af[mi][2], af[mi][3],
                             bg[ni][0], bg[ni][1]);
                    mma_tf32(acc_u[mi][ni], af[mi][0], af[mi][1], af[mi][2], af[mi][3],
                             bu[ni][0], bu[ni][1]);
                }
        }
        __syncthreads();

        if (j + 3 < nK) {
            const int k0 = (j+3)*32;
#pragma unroll
            for (int i = 0; i < 4; i++) {
                cpa16(dstA + (s*TSZ + i*32*LDSW)*4,     Ag + (long)i*32*HID + k0);
                cpa16(dstA + ((3+s)*TSZ + i*32*LDSW)*4, Gg + (long)i*32*HID + k0);
                cpa16(dstA + ((6+s)*TSZ + i*32*LDSW)*4, Ug + (long)i*32*HID + k0);
            }
        }
        CP_COMMIT();
    }

    // epilogue: inter = tf32( silu(g) * u )
#pragma unroll
    for (int mi = 0; mi < 4; mi++) {
#pragma unroll
        for (int ni = 0; ni < 4; ni++) {
            long r0 = bm + wm*64 + mi*16 + grp;
            long c0 = bn + wn*32 + ni*8 + tig*2;
            float gv, uv; float2 o;
            gv = acc_g[mi][ni][0]; uv = acc_u[mi][ni][0];
            o.x = __uint_as_float(f2tf32((gv / (1.f + __expf(-gv))) * uv));
            gv = acc_g[mi][ni][1]; uv = acc_u[mi][ni][1];
            o.y = __uint_as_float(f2tf32((gv / (1.f + __expf(-gv))) * uv));
            *(float2*)(inter + r0*INTER + c0) = o;
            gv = acc_g[mi][ni][2]; uv = acc_u[mi][ni][2];
            o.x = __uint_as_float(f2tf32((gv / (1.f + __expf(-gv))) * uv));
            gv = acc_g[mi][ni][3]; uv = acc_u[mi][ni][3];
            o.y = __uint_as_float(f2tf32((gv / (1.f + __expf(-gv))) * uv));
            *(float2*)(inter + (r0+8)*INTER + c0) = o;
        }
    }
}

// ============================================================================
// Down GEMM: out = inter * Wd^T, K = 5504
// ============================================================================
#define DN_SMEM_BYTES (6*TSZ*4)   // 110592

__global__ void __launch_bounds__(256,1)
gemm_down(const float* __restrict__ A, const float* __restrict__ B, float* __restrict__ C)
{
    extern __shared__ float smem[];
    const uint32_t sb = smem_u32(smem);

    const int tid  = threadIdx.x;
    const int wid  = tid >> 5;
    const int lane = tid & 31;
    const int grp  = lane >> 2;
    const int tig  = lane & 3;
    const int wm   = wid >> 2;
    const int wn   = wid & 3;

    const int NBN = HID/128;   // 16
    const int GM  = 16;
    int bid = blockIdx.x;
    int g   = bid / (GM*NBN);
    int r   = bid % (GM*NBN);
    const long bm = (long)(g*GM + (r % GM)) * 128;
    const int  bn = (r / GM) * 128;

    const int ldr = tid >> 3;
    const int ldc = tid & 7;

    const float* Ag = A + (bm + ldr)*(long)INTER + ldc*4;
    const float* Bg = B + (long)(bn + ldr)*INTER + ldc*4;
    const uint32_t dstA = sb + (ldr*LDSW + ldc*4)*4;

    float acc[4][4][4];
#pragma unroll
    for (int mi = 0; mi < 4; mi++)
#pragma unroll
        for (int ni = 0; ni < 4; ni++)
#pragma unroll
            for (int q = 0; q < 4; q++) acc[mi][ni][q] = 0.f;

    const int nK = INTER/32;   // 172

#pragma unroll
    for (int p = 0; p < 3; p++) {
        const int k0 = p*32;
#pragma unroll
        for (int i = 0; i < 4; i++) {
            cpa16(dstA + (p*TSZ + i*32*LDSW)*4,     Ag + (long)i*32*INTER + k0);
            cpa16(dstA + ((3+p)*TSZ + i*32*LDSW)*4, Bg + (long)i*32*INTER + k0);
        }
        CP_COMMIT();
    }

    for (int j = 0; j < nK; j++) {
        const int s = j % 3;
        CP_WAIT2();
        __syncthreads();

        const float* As = smem + s*TSZ;
        const float* Bs = smem + (3+s)*TSZ;

#pragma unroll
        for (int ks = 0; ks < 4; ks++) {
            const int k0 = ks*8;
            uint32_t af[4][4], bf[4][2];
#pragma unroll
            for (int mi = 0; mi < 4; mi++) {
                int rr = wm*64 + mi*16 + grp;
                af[mi][0] = __float_as_uint(As[rr*LDSW + k0 + tig]);
                af[mi][1] = __float_as_uint(As[(rr+8)*LDSW + k0 + tig]);
                af[mi][2] = __float_as_uint(As[rr*LDSW + k0 + tig + 4]);
                af[mi][3] = __float_as_uint(As[(rr+8)*LDSW + k0 + tig + 4]);
            }
#pragma unroll
            for (int ni = 0; ni < 4; ni++) {
                int cc = wn*32 + ni*8 + grp;
                bf[ni][0] = __float_as_uint(Bs[cc*LDSW + k0 + tig]);
                bf[ni][1] = __float_as_uint(Bs[cc*LDSW + k0 + tig + 4]);
            }
#pragma unroll
            for (int mi = 0; mi < 4; mi++)
#pragma unroll
                for (int ni = 0; ni < 4; ni++)
                    mma_tf32(acc[mi][ni], af[mi][0], af[mi][1], af[mi][2], af[mi][3],
                             bf[ni][0], bf[ni][1]);
        }
        __syncthreads();

        if (j + 3 < nK) {
            const int k0 = (j+3)*32;
#pragma unroll
            for (int i = 0; i < 4; i++) {
                cpa16(dstA + (s*TSZ + i*32*LDSW)*4,     Ag + (long)i*32*INTER + k0);
                cpa16(dstA + ((3+s)*TSZ + i*32*LDSW)*4, Bg + (long)i*32*INTER + k0);
            }
        }
        CP_COMMIT();
    }

#pragma unroll
    for (int mi = 0; mi < 4; mi++) {
#pragma unroll
        for (int ni = 0; ni < 4; ni++) {
            long r0 = bm + wm*64 + mi*16 + grp;
            long c0 = bn + wn*32 + ni*8 + tig*2;
            *(float2*)(C + r0*HID + c0)     = make_float2(acc[mi][ni][0], acc[mi][ni][1]);
            *(float2*)(C + (r0+8)*HID + c0) = make_float2(acc[mi][ni][2], acc[mi][ni][3]);
        }
    }
}

// ---------------- elementwise / reductions ----------------
__global__ void cvt_kernel(const float4* __restrict__ in, float4* __restrict__ out, long n4){
    long i = (long)blockIdx.x * blockDim.x + threadIdx.x;
    if (i >= n4) return;
    float4 v = in[i];
    v.x = __uint_as_float(f2tf32(v.x));
    v.y = __uint_as_float(f2tf32(v.y));
    v.z = __uint_as_float(f2tf32(v.z));
    v.w = __uint_as_float(f2tf32(v.w));
    out[i] = v;
}

__global__ void rowsq_kernel(const float* __restrict__ wup, float* __restrict__ out){
    int row  = blockIdx.x * 8 + (threadIdx.x >> 5);
    int lane = threadIdx.x & 31;
    if (row >= INTER) return;
    const float4* p = (const float4*)(wup + (long)row * HID);
    float s = 0.f;
#pragma unroll 4
    for (int j = lane; j < HID/4; j += 32) {
        float4 v = p[j];
        s += v.x*v.x + v.y*v.y + v.z*v.z + v.w*v.w;
    }
#pragma unroll
    for (int off = 16; off > 0; off >>= 1) s += __shfl_xor_sync(0xffffffffu, s, off);
    if (lane == 0) out[row] = s;
}

__global__ void impacts_p1(const float* __restrict__ inter, float* __restrict__ part){
    int i = blockIdx.x * 256 + threadIdx.x;
    int sc = blockIdx.y;
    if (i >= INTER) return;
    const float* p = inter + (long)sc * 256 * INTER + i;
    float s = 0.f;
#pragma unroll 8
    for (int rr = 0; rr < 256; rr++) { float v = p[(long)rr * INTER]; s += v*v; }
    part[(long)sc * INTER + i] = s;
}

__global__ void impacts_p2(const float* __restrict__ part, const float* __restrict__ rowsq,
                           float* __restrict__ out){
    int idx = blockIdx.x * 256 + threadIdx.x;
    if (idx >= BATCH * INTER) return;
    int b = idx / INTER, i = idx - b * INTER;
    float s = 0.f;
#pragma unroll
    for (int k = 0; k < 8; k++) s += part[(long)(b*8 + k) * INTER + i];
    out[idx] = sqrtf(s * rowsq[i]);
}

// ---------------- launch ----------------
extern "C" void kernel_launch(void* const* d_in, const int* in_sizes, int n_in,
                              void* d_out, int out_size)
{
    const float* X  = (const float*)d_in[0];
    const float* Wg = (const float*)d_in[1];
    const float* Wu = (const float*)d_in[2];
    const float* Wd = (const float*)d_in[3];
    float* out = (float*)d_out;

    float *Xc, *Wgc, *Wuc, *Wdc, *inter, *rsq, *part;
    cudaGetSymbolAddress((void**)&Xc,  g_Xc);
    cudaGetSymbolAddress((void**)&Wgc, g_Wgc);
    cudaGetSymbolAddress((void**)&Wuc, g_Wuc);
    cudaGetSymbolAddress((void**)&Wdc, g_Wdc);
    cudaGetSymbolAddress((void**)&inter, g_inter);
    cudaGetSymbolAddress((void**)&rsq, g_rowsq);
    cudaGetSymbolAddress((void**)&part, g_part);

    cudaFuncSetAttribute(gemm_gu,   cudaFuncAttributeMaxDynamicSharedMemorySize, GU_SMEM_BYTES);
    cudaFuncSetAttribute(gemm_down, cudaFuncAttributeMaxDynamicSharedMemorySize, DN_SMEM_BYTES);

    // 0) tf32-round inputs once
    long nX = (long)MTOK * HID / 4, nW = (long)INTER * HID / 4;
    cvt_kernel<<<(unsigned)((nX + 255)/256), 256>>>((const float4*)X,  (float4*)Xc,  nX);
    cvt_kernel<<<(unsigned)((nW + 255)/256), 256>>>((const float4*)Wg, (float4*)Wgc, nW);
    cvt_kernel<<<(unsigned)((nW + 255)/256), 256>>>((const float4*)Wu, (float4*)Wuc, nW);
    cvt_kernel<<<(unsigned)((nW + 255)/256), 256>>>((const float4*)Wd, (float4*)Wdc, nW);

    // 1) fused gate/up + SwiGLU
    gemm_gu<<<(INTER/128)*(MTOK/128), 256, GU_SMEM_BYTES>>>(Xc, Wgc, Wuc, inter);

    // 2) impacts
    rowsq_kernel<<<(INTER + 7)/8, 256>>>(Wu, rsq);
    dim3 gp1((INTER + 255)/256, 32);
    impacts_p1<<<gp1, 256>>>(inter, part);
    impacts_p2<<<(BATCH*INTER + 255)/256, 256>>>(part, rsq, out + OUT_ELEMS);

    // 3) down projection
    gemm_down<<<(HID/128)*(MTOK/128), 256, DN_SMEM_BYTES>>>(inter, Wdc, out);
}